// round 11
// baseline (speedup 1.0000x reference)
#include <cuda_runtime.h>
#include <cstdint>

#define N_NODES 50000
#define N_FEAT  128
#define N_HID   64
#define N_EDGES 800000
#define LRELU   0.05f
#define SCAN_BLOCKS ((N_NODES + 255) / 256)   // 196

// Scratch (static device globals; no allocation allowed)
__device__ float g_ht[N_NODES * N_HID];   // h_transformed  [N, 64]
__device__ float g_e1[N_NODES];           // h_t[i] . a_w[:64]
__device__ float g_e2[N_NODES];           // h_t[i] . a_w[64:]
__device__ float g_hsum[N_NODES];         // segment sum of hexp by src
__device__ int   g_count[N_NODES];        // out-degree histogram (by src)
__device__ int   g_off[N_NODES];          // CSR offsets
__device__ int   g_cursor[N_NODES];       // placement cursors
__device__ int   g_bsum[SCAN_BLOCKS];     // per-block count sums
__device__ int   g_boff[SCAN_BLOCKS];     // per-block scan bases
__device__ int4  g_ea[N_EDGES];           // packed {dst, h-bits, edge_id, 0}, segment-ordered
__device__ int   g_idx64;                 // 1 if edge_index is int64, 0 if int32

// ---------------------------------------------------------------------------
__device__ __forceinline__ int load_idx(const void* ei, int row, int e)
{
    long long v;
    if (g_idx64) v = ((const long long*)ei)[(long long)row * N_EDGES + e];
    else         v = ((const int*)ei)[(long long)row * N_EDGES + e];
    if (v < 0) v = 0;
    if (v >= N_NODES) v = N_NODES - 1;
    return (int)v;
}

// Parallel dtype probe: 32 lanes x 2 samples, ballot instead of serial chain.
__global__ void k_detect(const void* ei)
{
    if (blockIdx.x != 0) return;
    const long long* p = (const long long*)ei;
    int lane = threadIdx.x & 31;
    long long v0 = p[lane];
    long long v1 = p[32 + lane];
    int bad = (v0 < 0 || v0 >= N_NODES || v1 < 0 || v1 >= N_NODES);
    unsigned m = __ballot_sync(0xFFFFFFFFu, bad);
    if (lane == 0) g_idx64 = (m == 0);
}

__global__ void k_zero()
{
    int i = blockIdx.x * blockDim.x + threadIdx.x;
    if (i < N_NODES) { g_count[i] = 0; g_hsum[i] = 0.0f; }
}

// ---------------------------------------------------------------------------
// Kernel 1: h_t = x @ W_fc with 2x4 register tiling; fused e1/e2 epilogue.
// Tile 32 rows x 64 cols. Smem 48KB (static limit).
// ---------------------------------------------------------------------------
__global__ void k_gemm(const float* __restrict__ x,
                       const float* __restrict__ W,
                       const float* __restrict__ aw)
{
    __shared__ float Ws[N_FEAT * N_HID];   // 32 KB  [k][col]
    __shared__ float xs[32 * N_FEAT];      // 16 KB  [row][k]

    const int tid = threadIdx.x;
    const int tx  = tid & 15;
    const int ty  = tid >> 4;
    const int row0 = blockIdx.x * 32;

    {
        const float4* Wg = (const float4*)W;
        float4* Wsm = (float4*)Ws;
        #pragma unroll
        for (int i = 0; i < 8; i++) Wsm[tid + i * 256] = Wg[tid + i * 256];
    }
    {
        float4* xsm = (float4*)xs;
        #pragma unroll
        for (int i = 0; i < 4; i++) {
            int i4 = tid + i * 256;
            int row = row0 + (i4 >> 5);
            float4 v = make_float4(0.f, 0.f, 0.f, 0.f);
            if (row < N_NODES)
                v = ((const float4*)x)[(long long)row * 32 + (i4 & 31)];
            xsm[i4] = v;
        }
    }
    const float4 a1v = ((const float4*)aw)[tx];
    const float4 a2v = ((const float4*)(aw + N_HID))[tx];
    __syncthreads();

    float acc[2][4];
    #pragma unroll
    for (int i = 0; i < 2; i++)
        #pragma unroll
        for (int j = 0; j < 4; j++) acc[i][j] = 0.0f;

    #pragma unroll 8
    for (int k = 0; k < N_FEAT; k++) {
        float4 w = *(const float4*)&Ws[k * N_HID + tx * 4];
        float x0 = xs[(ty * 2 + 0) * N_FEAT + k];
        float x1 = xs[(ty * 2 + 1) * N_FEAT + k];
        acc[0][0] = fmaf(x0, w.x, acc[0][0]);
        acc[0][1] = fmaf(x0, w.y, acc[0][1]);
        acc[0][2] = fmaf(x0, w.z, acc[0][2]);
        acc[0][3] = fmaf(x0, w.w, acc[0][3]);
        acc[1][0] = fmaf(x1, w.x, acc[1][0]);
        acc[1][1] = fmaf(x1, w.y, acc[1][1]);
        acc[1][2] = fmaf(x1, w.z, acc[1][2]);
        acc[1][3] = fmaf(x1, w.w, acc[1][3]);
    }

    #pragma unroll
    for (int i = 0; i < 2; i++) {
        int row = row0 + ty * 2 + i;
        float p1 = acc[i][0] * a1v.x + acc[i][1] * a1v.y +
                   acc[i][2] * a1v.z + acc[i][3] * a1v.w;
        float p2 = acc[i][0] * a2v.x + acc[i][1] * a2v.y +
                   acc[i][2] * a2v.z + acc[i][3] * a2v.w;
        #pragma unroll
        for (int o = 8; o > 0; o >>= 1) {
            p1 += __shfl_xor_sync(0xFFFFFFFFu, p1, o);
            p2 += __shfl_xor_sync(0xFFFFFFFFu, p2, o);
        }
        if (row < N_NODES) {
            *(float4*)&g_ht[(long long)row * N_HID + tx * 4] =
                make_float4(acc[i][0], acc[i][1], acc[i][2], acc[i][3]);
            if (tx == 0) { g_e1[row] = p1; g_e2[row] = p2; }
        }
    }
}

// ---------------------------------------------------------------------------
// Kernel 2: src out-degree histogram (src row only)
// ---------------------------------------------------------------------------
__global__ void k_hist(const void* __restrict__ ei)
{
    int e = blockIdx.x * blockDim.x + threadIdx.x;
    if (e >= N_EDGES) return;
    atomicAdd(&g_count[load_idx(ei, 0, e)], 1);
}

// ---------------------------------------------------------------------------
// Hierarchical exclusive scan: A) block sums  B) scan of sums  C) offsets
// ---------------------------------------------------------------------------
__global__ void k_scanA()
{
    __shared__ int sh[256];
    int idx = blockIdx.x * 256 + threadIdx.x;
    int v = (idx < N_NODES) ? g_count[idx] : 0;
    sh[threadIdx.x] = v;
    __syncthreads();
    for (int o = 128; o > 0; o >>= 1) {
        if (threadIdx.x < o) sh[threadIdx.x] += sh[threadIdx.x + o];
        __syncthreads();
    }
    if (threadIdx.x == 0) g_bsum[blockIdx.x] = sh[0];
}

__global__ void k_scanB()
{
    __shared__ int sh[256];
    int t = threadIdx.x;
    sh[t] = (t < SCAN_BLOCKS) ? g_bsum[t] : 0;
    __syncthreads();
    for (int o = 1; o < 256; o <<= 1) {
        int v = (t >= o) ? sh[t - o] : 0;
        __syncthreads();
        sh[t] += v;
        __syncthreads();
    }
    if (t < SCAN_BLOCKS) g_boff[t] = (t == 0) ? 0 : sh[t - 1];
}

__global__ void k_scanC()
{
    __shared__ int sh[256];
    int t = threadIdx.x;
    int idx = blockIdx.x * 256 + t;
    int v = (idx < N_NODES) ? g_count[idx] : 0;
    sh[t] = v;
    __syncthreads();
    for (int o = 1; o < 256; o <<= 1) {
        int u = (t >= o) ? sh[t - o] : 0;
        __syncthreads();
        sh[t] += u;
        __syncthreads();
    }
    if (idx < N_NODES) {
        int off = g_boff[blockIdx.x] + sh[t] - v;   // exclusive
        g_off[idx] = off;
        g_cursor[idx] = off;
    }
}

// ---------------------------------------------------------------------------
// Kernel 3: fused score + hsum + place. Normalization deferred to accum,
// so this needs no completed hsum. One 16B ST.128 scatter per edge.
// ---------------------------------------------------------------------------
__global__ void k_score_place(const void* __restrict__ ei,
                              const float* __restrict__ ab)
{
    int e = blockIdx.x * blockDim.x + threadIdx.x;
    if (e >= N_EDGES) return;
    int s = load_idx(ei, 0, e);
    int d = load_idx(ei, 1, e);
    float z = g_e1[s] + g_e2[d] + ab[0];
    z = (z >= 0.0f) ? z : LRELU * z;
    float h = __expf(z);
    atomicAdd(&g_hsum[s], h);
    int pos = atomicAdd(&g_cursor[s], 1);
    g_ea[pos] = make_int4(d, __float_as_int(h), e, 0);
}

// ---------------------------------------------------------------------------
// Kernel 4: per-node accumulate + normalize + alpha scatter.
// 4 nodes per 256-thread block. out = (sum h*ht) * inv; alpha = h * inv.
// ---------------------------------------------------------------------------
__global__ void k_accum(float* __restrict__ out,
                        float* __restrict__ alpha_out)
{
    const int g = threadIdx.x >> 6;    // node within block (0..3)
    const int c = threadIdx.x & 63;    // channel
    const int s = blockIdx.x * 4 + g;  // 12500*4 = 50000 exact
    const int off = g_off[s];
    const int cnt = g_count[s];
    const float inv = (cnt > 0) ? (1.0f / g_hsum[s]) : 0.0f;

    float a0 = 0.f, a1 = 0.f, a2 = 0.f, a3 = 0.f;
    int j = 0;
    for (; j + 4 <= cnt; j += 4) {
        int4 e0 = g_ea[off + j + 0];
        int4 e1 = g_ea[off + j + 1];
        int4 e2 = g_ea[off + j + 2];
        int4 e3 = g_ea[off + j + 3];
        a0 = fmaf(__int_as_float(e0.y), g_ht[(long long)e0.x * N_HID + c], a0);
        a1 = fmaf(__int_as_float(e1.y), g_ht[(long long)e1.x * N_HID + c], a1);
        a2 = fmaf(__int_as_float(e2.y), g_ht[(long long)e2.x * N_HID + c], a2);
        a3 = fmaf(__int_as_float(e3.y), g_ht[(long long)e3.x * N_HID + c], a3);
        if (c == ((j + 0) & 63)) alpha_out[e0.z] = __int_as_float(e0.y) * inv;
        if (c == ((j + 1) & 63)) alpha_out[e1.z] = __int_as_float(e1.y) * inv;
        if (c == ((j + 2) & 63)) alpha_out[e2.z] = __int_as_float(e2.y) * inv;
        if (c == ((j + 3) & 63)) alpha_out[e3.z] = __int_as_float(e3.y) * inv;
    }
    for (; j < cnt; j++) {
        int4 ee = g_ea[off + j];
        a0 = fmaf(__int_as_float(ee.y), g_ht[(long long)ee.x * N_HID + c], a0);
        if (c == (j & 63)) alpha_out[ee.z] = __int_as_float(ee.y) * inv;
    }
    out[(long long)s * N_HID + c] = ((a0 + a1) + (a2 + a3)) * inv;
}

// ---------------------------------------------------------------------------
extern "C" void kernel_launch(void* const* d_in, const int* in_sizes, int n_in,
                              void* d_out, int out_size)
{
    const float* x   = (const float*)d_in[0];
    const void*  ei  = d_in[1];                 // [2, E] int32 or int64
    const float* Wfc = (const float*)d_in[2];
    const float* aw  = (const float*)d_in[3];
    const float* ab  = (const float*)d_in[4];

    float* out   = (float*)d_out;                   // [N, 64]
    float* alpha = (float*)d_out + N_NODES * N_HID; // [E]

    k_detect<<<1, 32>>>(ei);
    k_zero<<<(N_NODES + 255) / 256, 256>>>();
    k_hist<<<(N_EDGES + 255) / 256, 256>>>(ei);
    k_scanA<<<SCAN_BLOCKS, 256>>>();
    k_scanB<<<1, 256>>>();
    k_scanC<<<SCAN_BLOCKS, 256>>>();
    k_gemm<<<(N_NODES + 31) / 32, 256>>>(x, Wfc, aw);
    k_score_place<<<(N_EDGES + 255) / 256, 256>>>(ei, ab);
    k_accum<<<N_NODES / 4, 256>>>(out, alpha);
}

// round 13
// speedup vs baseline: 1.1379x; 1.1379x over previous
#include <cuda_runtime.h>
#include <cstdint>

#define N_NODES 50000
#define N_FEAT  128
#define N_HID   64
#define N_EDGES 800000
#define LRELU   0.05f
#define SCAN_BLOCKS ((N_NODES + 255) / 256)   // 196

// Scratch (static device globals; no allocation allowed)
__device__ float g_ht[N_NODES * N_HID];   // h_transformed  [N, 64]
__device__ float g_e1[N_NODES];           // h_t[i] . a_w[:64]
__device__ float g_e2[N_NODES];           // h_t[i] . a_w[64:]
__device__ float g_hexp[N_EDGES];         // per-edge exp(leakyrelu(z))
__device__ float g_hsum[N_NODES];         // segment sum of hexp by src
__device__ int   g_count[N_NODES];        // out-degree histogram (by src)
__device__ int   g_off[N_NODES];          // CSR offsets
__device__ int   g_cursor[N_NODES];       // placement cursors
__device__ int   g_bsum[SCAN_BLOCKS];     // per-block count sums
__device__ int2  g_ea[N_EDGES];           // packed {dst, alpha-bits}, segment-ordered
__device__ int   g_idx64;                 // 1 if edge_index is int64, 0 if int32

// ---------------------------------------------------------------------------
__device__ __forceinline__ int load_idx(const void* ei, int row, int e)
{
    long long v;
    if (g_idx64) v = ((const long long*)ei)[(long long)row * N_EDGES + e];
    else         v = ((const int*)ei)[(long long)row * N_EDGES + e];
    if (v < 0) v = 0;
    if (v >= N_NODES) v = N_NODES - 1;
    return (int)v;
}

// ---------------------------------------------------------------------------
// Kernel 0: zero accumulators; block 0 also probes index dtype (ballot).
// ---------------------------------------------------------------------------
__global__ void k_zero(const void* ei)
{
    int i = blockIdx.x * blockDim.x + threadIdx.x;
    if (i < N_NODES) { g_count[i] = 0; g_hsum[i] = 0.0f; }
    if (blockIdx.x == 0 && threadIdx.x < 32) {
        const long long* p = (const long long*)ei;
        int lane = threadIdx.x;
        long long v0 = p[lane];
        long long v1 = p[32 + lane];
        int bad = (v0 < 0 || v0 >= N_NODES || v1 < 0 || v1 >= N_NODES);
        unsigned m = __ballot_sync(0xFFFFFFFFu, bad);
        if (lane == 0) g_idx64 = (m == 0);
    }
}

// ---------------------------------------------------------------------------
// Kernel 1: h_t = x @ W_fc with 2x4 register tiling; fused e1/e2 epilogue.
// Tile 32 rows x 64 cols. Smem 48KB (static limit).
// ---------------------------------------------------------------------------
__global__ void k_gemm(const float* __restrict__ x,
                       const float* __restrict__ W,
                       const float* __restrict__ aw)
{
    __shared__ float Ws[N_FEAT * N_HID];   // 32 KB  [k][col]
    __shared__ float xs[32 * N_FEAT];      // 16 KB  [row][k]

    const int tid = threadIdx.x;
    const int tx  = tid & 15;
    const int ty  = tid >> 4;
    const int row0 = blockIdx.x * 32;

    {
        const float4* Wg = (const float4*)W;
        float4* Wsm = (float4*)Ws;
        #pragma unroll
        for (int i = 0; i < 8; i++) Wsm[tid + i * 256] = Wg[tid + i * 256];
    }
    {
        float4* xsm = (float4*)xs;
        #pragma unroll
        for (int i = 0; i < 4; i++) {
            int i4 = tid + i * 256;
            int row = row0 + (i4 >> 5);
            float4 v = make_float4(0.f, 0.f, 0.f, 0.f);
            if (row < N_NODES)
                v = ((const float4*)x)[(long long)row * 32 + (i4 & 31)];
            xsm[i4] = v;
        }
    }
    const float4 a1v = ((const float4*)aw)[tx];
    const float4 a2v = ((const float4*)(aw + N_HID))[tx];
    __syncthreads();

    float acc[2][4];
    #pragma unroll
    for (int i = 0; i < 2; i++)
        #pragma unroll
        for (int j = 0; j < 4; j++) acc[i][j] = 0.0f;

    #pragma unroll 8
    for (int k = 0; k < N_FEAT; k++) {
        float4 w = *(const float4*)&Ws[k * N_HID + tx * 4];
        float x0 = xs[(ty * 2 + 0) * N_FEAT + k];
        float x1 = xs[(ty * 2 + 1) * N_FEAT + k];
        acc[0][0] = fmaf(x0, w.x, acc[0][0]);
        acc[0][1] = fmaf(x0, w.y, acc[0][1]);
        acc[0][2] = fmaf(x0, w.z, acc[0][2]);
        acc[0][3] = fmaf(x0, w.w, acc[0][3]);
        acc[1][0] = fmaf(x1, w.x, acc[1][0]);
        acc[1][1] = fmaf(x1, w.y, acc[1][1]);
        acc[1][2] = fmaf(x1, w.z, acc[1][2]);
        acc[1][3] = fmaf(x1, w.w, acc[1][3]);
    }

    #pragma unroll
    for (int i = 0; i < 2; i++) {
        int row = row0 + ty * 2 + i;
        float p1 = acc[i][0] * a1v.x + acc[i][1] * a1v.y +
                   acc[i][2] * a1v.z + acc[i][3] * a1v.w;
        float p2 = acc[i][0] * a2v.x + acc[i][1] * a2v.y +
                   acc[i][2] * a2v.z + acc[i][3] * a2v.w;
        #pragma unroll
        for (int o = 8; o > 0; o >>= 1) {
            p1 += __shfl_xor_sync(0xFFFFFFFFu, p1, o);
            p2 += __shfl_xor_sync(0xFFFFFFFFu, p2, o);
        }
        if (row < N_NODES) {
            *(float4*)&g_ht[(long long)row * N_HID + tx * 4] =
                make_float4(acc[i][0], acc[i][1], acc[i][2], acc[i][3]);
            if (tx == 0) { g_e1[row] = p1; g_e2[row] = p2; }
        }
    }
}

// ---------------------------------------------------------------------------
// Kernel 2: fused score + histogram + h_sum. One edge pass.
// ---------------------------------------------------------------------------
__global__ void k_score_hist(const void* __restrict__ ei,
                             const float* __restrict__ ab)
{
    int e = blockIdx.x * blockDim.x + threadIdx.x;
    if (e >= N_EDGES) return;
    int s = load_idx(ei, 0, e);
    int d = load_idx(ei, 1, e);
    float z = g_e1[s] + g_e2[d] + ab[0];
    z = (z >= 0.0f) ? z : LRELU * z;
    float h = __expf(z);
    g_hexp[e] = h;
    atomicAdd(&g_count[s], 1);
    atomicAdd(&g_hsum[s], h);
}

// ---------------------------------------------------------------------------
// Scan A: per-256-block sums of counts.
// ---------------------------------------------------------------------------
__global__ void k_scanA()
{
    __shared__ int sh[256];
    int idx = blockIdx.x * 256 + threadIdx.x;
    int v = (idx < N_NODES) ? g_count[idx] : 0;
    sh[threadIdx.x] = v;
    __syncthreads();
    for (int o = 128; o > 0; o >>= 1) {
        if (threadIdx.x < o) sh[threadIdx.x] += sh[threadIdx.x + o];
        __syncthreads();
    }
    if (threadIdx.x == 0) g_bsum[blockIdx.x] = sh[0];
}

// ---------------------------------------------------------------------------
// Scan C: each block redundantly scans all 196 block sums in smem (cheap),
// then does its local exclusive scan -> offsets + cursors. (scanB fused.)
// ---------------------------------------------------------------------------
__global__ void k_scanC()
{
    __shared__ int sb[256];
    __shared__ int sh[256];
    int t = threadIdx.x;

    sb[t] = (t < SCAN_BLOCKS) ? g_bsum[t] : 0;
    __syncthreads();
    for (int o = 1; o < 256; o <<= 1) {
        int v = (t >= o) ? sb[t - o] : 0;
        __syncthreads();
        sb[t] += v;
        __syncthreads();
    }
    int base = (blockIdx.x == 0) ? 0 : sb[blockIdx.x - 1];

    int idx = blockIdx.x * 256 + t;
    int v = (idx < N_NODES) ? g_count[idx] : 0;
    sh[t] = v;
    __syncthreads();
    for (int o = 1; o < 256; o <<= 1) {
        int u = (t >= o) ? sh[t - o] : 0;
        __syncthreads();
        sh[t] += u;
        __syncthreads();
    }
    if (idx < N_NODES) {
        int off = base + sh[t] - v;   // exclusive
        g_off[idx] = off;
        g_cursor[idx] = off;
    }
}

// ---------------------------------------------------------------------------
// Kernel 3: place. alpha = hexp/hsum[src] -> alpha_out coalesced; one packed
// 8B {dst, alpha} scattered store into segment order.
// ---------------------------------------------------------------------------
__global__ void k_place(const void* __restrict__ ei,
                        float* __restrict__ alpha_out)
{
    int e = blockIdx.x * blockDim.x + threadIdx.x;
    if (e >= N_EDGES) return;
    int s = load_idx(ei, 0, e);
    int d = load_idx(ei, 1, e);
    float a = g_hexp[e] / g_hsum[s];
    alpha_out[e] = a;
    int pos = atomicAdd(&g_cursor[s], 1);
    g_ea[pos] = make_int2(d, __float_as_int(a));
}

// ---------------------------------------------------------------------------
// Kernel 4: per-node accumulate, 4 nodes per 256-thread block.
// Pure gather: acc += alpha * h_t[dst][c]. No reductions, no scatters.
// ---------------------------------------------------------------------------
__global__ void k_accum(float* __restrict__ out)
{
    const int g = threadIdx.x >> 6;    // node within block (0..3)
    const int c = threadIdx.x & 63;    // channel
    const int s = blockIdx.x * 4 + g;  // 12500*4 = 50000 exact
    const int off = g_off[s];
    const int cnt = g_count[s];

    float a0 = 0.f, a1 = 0.f, a2 = 0.f, a3 = 0.f;
    int j = 0;
    for (; j + 4 <= cnt; j += 4) {
        int2 e0 = __ldg(&g_ea[off + j + 0]);
        int2 e1 = __ldg(&g_ea[off + j + 1]);
        int2 e2 = __ldg(&g_ea[off + j + 2]);
        int2 e3 = __ldg(&g_ea[off + j + 3]);
        a0 = fmaf(__int_as_float(e0.y), __ldg(&g_ht[(long long)e0.x * N_HID + c]), a0);
        a1 = fmaf(__int_as_float(e1.y), __ldg(&g_ht[(long long)e1.x * N_HID + c]), a1);
        a2 = fmaf(__int_as_float(e2.y), __ldg(&g_ht[(long long)e2.x * N_HID + c]), a2);
        a3 = fmaf(__int_as_float(e3.y), __ldg(&g_ht[(long long)e3.x * N_HID + c]), a3);
    }
    for (; j < cnt; j++) {
        int2 ee = __ldg(&g_ea[off + j]);
        a0 = fmaf(__int_as_float(ee.y), __ldg(&g_ht[(long long)ee.x * N_HID + c]), a0);
    }
    out[(long long)s * N_HID + c] = (a0 + a1) + (a2 + a3);
}

// ---------------------------------------------------------------------------
extern "C" void kernel_launch(void* const* d_in, const int* in_sizes, int n_in,
                              void* d_out, int out_size)
{
    const float* x   = (const float*)d_in[0];
    const void*  ei  = d_in[1];                 // [2, E] int32 or int64
    const float* Wfc = (const float*)d_in[2];
    const float* aw  = (const float*)d_in[3];
    const float* ab  = (const float*)d_in[4];

    float* out   = (float*)d_out;                   // [N, 64]
    float* alpha = (float*)d_out + N_NODES * N_HID; // [E]

    k_zero<<<(N_NODES + 255) / 256, 256>>>(ei);
    k_gemm<<<(N_NODES + 31) / 32, 256>>>(x, Wfc, aw);
    k_score_hist<<<(N_EDGES + 255) / 256, 256>>>(ei, ab);
    k_scanA<<<SCAN_BLOCKS, 256>>>();
    k_scanC<<<SCAN_BLOCKS, 256>>>();
    k_place<<<(N_EDGES + 255) / 256, 256>>>(ei, alpha);
    k_accum<<<N_NODES / 4, 256>>>(out);
}

// round 14
// speedup vs baseline: 1.2937x; 1.1369x over previous
#include <cuda_runtime.h>
#include <cstdint>

#define N_NODES 50000
#define N_FEAT  128
#define N_HID   64
#define N_EDGES 800000
#define LRELU   0.05f
#define SCAN_BLOCKS ((N_NODES + 255) / 256)   // 196

// Scratch (static device globals; no allocation allowed)
__device__ float g_ht[N_NODES * N_HID];   // h_transformed  [N, 64]
__device__ float g_e1[N_NODES];           // h_t[i] . a_w[:64]
__device__ float g_e2[N_NODES];           // h_t[i] . a_w[64:]
__device__ float g_hexp[N_EDGES];         // per-edge exp(leakyrelu(z))
__device__ float g_hsum[N_NODES];         // segment sum of hexp by src
__device__ int   g_count[N_NODES];        // out-degree histogram (by src)
__device__ int   g_off[N_NODES];          // CSR offsets
__device__ int   g_cursor[N_NODES];       // placement cursors
__device__ int   g_bsum[SCAN_BLOCKS];     // per-block count sums
__device__ int2  g_ea[N_EDGES];           // packed {dst, alpha-bits}, segment-ordered
__device__ int   g_idx64;                 // 1 if edge_index is int64, 0 if int32

// ---------------------------------------------------------------------------
__device__ __forceinline__ int load_idx(const void* ei, int row, int e)
{
    long long v;
    if (g_idx64) v = ((const long long*)ei)[(long long)row * N_EDGES + e];
    else         v = ((const int*)ei)[(long long)row * N_EDGES + e];
    if (v < 0) v = 0;
    if (v >= N_NODES) v = N_NODES - 1;
    return (int)v;
}

// ---------------------------------------------------------------------------
// Kernel 0: zero accumulators; block 0 also probes index dtype (ballot).
// ---------------------------------------------------------------------------
__global__ void k_zero(const void* ei)
{
    int i = blockIdx.x * blockDim.x + threadIdx.x;
    if (i < N_NODES) { g_count[i] = 0; g_hsum[i] = 0.0f; }
    if (blockIdx.x == 0 && threadIdx.x < 32) {
        const long long* p = (const long long*)ei;
        int lane = threadIdx.x;
        long long v0 = p[lane];
        long long v1 = p[32 + lane];
        int bad = (v0 < 0 || v0 >= N_NODES || v1 < 0 || v1 >= N_NODES);
        unsigned m = __ballot_sync(0xFFFFFFFFu, bad);
        if (lane == 0) g_idx64 = (m == 0);
    }
}

// ---------------------------------------------------------------------------
// Kernel 1: h_t = x @ W_fc with 2x4 register tiling; fused e1/e2 epilogue.
// Tile 32 rows x 64 cols. Smem 48KB (static limit).
// ---------------------------------------------------------------------------
__global__ void k_gemm(const float* __restrict__ x,
                       const float* __restrict__ W,
                       const float* __restrict__ aw)
{
    __shared__ float Ws[N_FEAT * N_HID];   // 32 KB  [k][col]
    __shared__ float xs[32 * N_FEAT];      // 16 KB  [row][k]

    const int tid = threadIdx.x;
    const int tx  = tid & 15;
    const int ty  = tid >> 4;
    const int row0 = blockIdx.x * 32;

    {
        const float4* Wg = (const float4*)W;
        float4* Wsm = (float4*)Ws;
        #pragma unroll
        for (int i = 0; i < 8; i++) Wsm[tid + i * 256] = Wg[tid + i * 256];
    }
    {
        float4* xsm = (float4*)xs;
        #pragma unroll
        for (int i = 0; i < 4; i++) {
            int i4 = tid + i * 256;
            int row = row0 + (i4 >> 5);
            float4 v = make_float4(0.f, 0.f, 0.f, 0.f);
            if (row < N_NODES)
                v = ((const float4*)x)[(long long)row * 32 + (i4 & 31)];
            xsm[i4] = v;
        }
    }
    const float4 a1v = ((const float4*)aw)[tx];
    const float4 a2v = ((const float4*)(aw + N_HID))[tx];
    __syncthreads();

    float acc[2][4];
    #pragma unroll
    for (int i = 0; i < 2; i++)
        #pragma unroll
        for (int j = 0; j < 4; j++) acc[i][j] = 0.0f;

    #pragma unroll 8
    for (int k = 0; k < N_FEAT; k++) {
        float4 w = *(const float4*)&Ws[k * N_HID + tx * 4];
        float x0 = xs[(ty * 2 + 0) * N_FEAT + k];
        float x1 = xs[(ty * 2 + 1) * N_FEAT + k];
        acc[0][0] = fmaf(x0, w.x, acc[0][0]);
        acc[0][1] = fmaf(x0, w.y, acc[0][1]);
        acc[0][2] = fmaf(x0, w.z, acc[0][2]);
        acc[0][3] = fmaf(x0, w.w, acc[0][3]);
        acc[1][0] = fmaf(x1, w.x, acc[1][0]);
        acc[1][1] = fmaf(x1, w.y, acc[1][1]);
        acc[1][2] = fmaf(x1, w.z, acc[1][2]);
        acc[1][3] = fmaf(x1, w.w, acc[1][3]);
    }

    #pragma unroll
    for (int i = 0; i < 2; i++) {
        int row = row0 + ty * 2 + i;
        float p1 = acc[i][0] * a1v.x + acc[i][1] * a1v.y +
                   acc[i][2] * a1v.z + acc[i][3] * a1v.w;
        float p2 = acc[i][0] * a2v.x + acc[i][1] * a2v.y +
                   acc[i][2] * a2v.z + acc[i][3] * a2v.w;
        #pragma unroll
        for (int o = 8; o > 0; o >>= 1) {
            p1 += __shfl_xor_sync(0xFFFFFFFFu, p1, o);
            p2 += __shfl_xor_sync(0xFFFFFFFFu, p2, o);
        }
        if (row < N_NODES) {
            *(float4*)&g_ht[(long long)row * N_HID + tx * 4] =
                make_float4(acc[i][0], acc[i][1], acc[i][2], acc[i][3]);
            if (tx == 0) { g_e1[row] = p1; g_e2[row] = p2; }
        }
    }
}

// ---------------------------------------------------------------------------
// Kernel 2: fused score + histogram + h_sum. One edge pass.
// ---------------------------------------------------------------------------
__global__ void k_score_hist(const void* __restrict__ ei,
                             const float* __restrict__ ab)
{
    int e = blockIdx.x * blockDim.x + threadIdx.x;
    if (e >= N_EDGES) return;
    int s = load_idx(ei, 0, e);
    int d = load_idx(ei, 1, e);
    float z = g_e1[s] + g_e2[d] + ab[0];
    z = (z >= 0.0f) ? z : LRELU * z;
    float h = __expf(z);
    g_hexp[e] = h;
    atomicAdd(&g_count[s], 1);
    atomicAdd(&g_hsum[s], h);
}

// ---------------------------------------------------------------------------
// Scan A: per-256-block sums of counts.
// ---------------------------------------------------------------------------
__global__ void k_scanA()
{
    __shared__ int sh[256];
    int idx = blockIdx.x * 256 + threadIdx.x;
    int v = (idx < N_NODES) ? g_count[idx] : 0;
    sh[threadIdx.x] = v;
    __syncthreads();
    for (int o = 128; o > 0; o >>= 1) {
        if (threadIdx.x < o) sh[threadIdx.x] += sh[threadIdx.x + o];
        __syncthreads();
    }
    if (threadIdx.x == 0) g_bsum[blockIdx.x] = sh[0];
}

// ---------------------------------------------------------------------------
// Scan C: each block redundantly scans all 196 block sums in smem (cheap),
// then does its local exclusive scan -> offsets + cursors. (scanB fused.)
// ---------------------------------------------------------------------------
__global__ void k_scanC()
{
    __shared__ int sb[256];
    __shared__ int sh[256];
    int t = threadIdx.x;

    sb[t] = (t < SCAN_BLOCKS) ? g_bsum[t] : 0;
    __syncthreads();
    for (int o = 1; o < 256; o <<= 1) {
        int v = (t >= o) ? sb[t - o] : 0;
        __syncthreads();
        sb[t] += v;
        __syncthreads();
    }
    int base = (blockIdx.x == 0) ? 0 : sb[blockIdx.x - 1];

    int idx = blockIdx.x * 256 + t;
    int v = (idx < N_NODES) ? g_count[idx] : 0;
    sh[t] = v;
    __syncthreads();
    for (int o = 1; o < 256; o <<= 1) {
        int u = (t >= o) ? sh[t - o] : 0;
        __syncthreads();
        sh[t] += u;
        __syncthreads();
    }
    if (idx < N_NODES) {
        int off = base + sh[t] - v;   // exclusive
        g_off[idx] = off;
        g_cursor[idx] = off;
    }
}

// ---------------------------------------------------------------------------
// Kernel 3: place. alpha = hexp/hsum[src] -> alpha_out coalesced; one packed
// 8B {dst, alpha} scattered store into segment order.
// ---------------------------------------------------------------------------
__global__ void k_place(const void* __restrict__ ei,
                        float* __restrict__ alpha_out)
{
    int e = blockIdx.x * blockDim.x + threadIdx.x;
    if (e >= N_EDGES) return;
    int s = load_idx(ei, 0, e);
    int d = load_idx(ei, 1, e);
    float a = g_hexp[e] / g_hsum[s];
    alpha_out[e] = a;
    int pos = atomicAdd(&g_cursor[s], 1);
    g_ea[pos] = make_int2(d, __float_as_int(a));
}

// ---------------------------------------------------------------------------
// Kernel 4: per-node accumulate, 16 nodes per 256-thread block.
// 16 threads/node, float4 gathers: 4x fewer LDG, 4x deeper per-thread MLP.
// Pure gather, no reductions, no scatters.
// ---------------------------------------------------------------------------
__global__ void k_accum(float* __restrict__ out)
{
    const int g = threadIdx.x >> 4;    // node within block (0..15)
    const int q = threadIdx.x & 15;    // float4 lane (channels 4q..4q+3)
    const int s = blockIdx.x * 16 + g; // 3125*16 = 50000 exact
    const int off = g_off[s];
    const int cnt = g_count[s];

    const float4* ht4 = (const float4*)g_ht;

    float4 A0 = make_float4(0.f, 0.f, 0.f, 0.f);
    float4 A1 = make_float4(0.f, 0.f, 0.f, 0.f);
    float4 A2 = make_float4(0.f, 0.f, 0.f, 0.f);
    float4 A3 = make_float4(0.f, 0.f, 0.f, 0.f);

    int j = 0;
    for (; j + 4 <= cnt; j += 4) {
        int2 e0 = g_ea[off + j + 0];
        int2 e1 = g_ea[off + j + 1];
        int2 e2 = g_ea[off + j + 2];
        int2 e3 = g_ea[off + j + 3];
        float4 v0 = ht4[e0.x * 16 + q];
        float4 v1 = ht4[e1.x * 16 + q];
        float4 v2 = ht4[e2.x * 16 + q];
        float4 v3 = ht4[e3.x * 16 + q];
        float a0 = __int_as_float(e0.y);
        float a1 = __int_as_float(e1.y);
        float a2 = __int_as_float(e2.y);
        float a3 = __int_as_float(e3.y);
        A0.x = fmaf(a0, v0.x, A0.x); A0.y = fmaf(a0, v0.y, A0.y);
        A0.z = fmaf(a0, v0.z, A0.z); A0.w = fmaf(a0, v0.w, A0.w);
        A1.x = fmaf(a1, v1.x, A1.x); A1.y = fmaf(a1, v1.y, A1.y);
        A1.z = fmaf(a1, v1.z, A1.z); A1.w = fmaf(a1, v1.w, A1.w);
        A2.x = fmaf(a2, v2.x, A2.x); A2.y = fmaf(a2, v2.y, A2.y);
        A2.z = fmaf(a2, v2.z, A2.z); A2.w = fmaf(a2, v2.w, A2.w);
        A3.x = fmaf(a3, v3.x, A3.x); A3.y = fmaf(a3, v3.y, A3.y);
        A3.z = fmaf(a3, v3.z, A3.z); A3.w = fmaf(a3, v3.w, A3.w);
    }
    for (; j < cnt; j++) {
        int2 ee = g_ea[off + j];
        float4 v = ht4[ee.x * 16 + q];
        float a = __int_as_float(ee.y);
        A0.x = fmaf(a, v.x, A0.x); A0.y = fmaf(a, v.y, A0.y);
        A0.z = fmaf(a, v.z, A0.z); A0.w = fmaf(a, v.w, A0.w);
    }

    float4 R;
    R.x = (A0.x + A1.x) + (A2.x + A3.x);
    R.y = (A0.y + A1.y) + (A2.y + A3.y);
    R.z = (A0.z + A1.z) + (A2.z + A3.z);
    R.w = (A0.w + A1.w) + (A2.w + A3.w);
    ((float4*)out)[s * 16 + q] = R;
}

// ---------------------------------------------------------------------------
extern "C" void kernel_launch(void* const* d_in, const int* in_sizes, int n_in,
                              void* d_out, int out_size)
{
    const float* x   = (const float*)d_in[0];
    const void*  ei  = d_in[1];                 // [2, E] int32 or int64
    const float* Wfc = (const float*)d_in[2];
    const float* aw  = (const float*)d_in[3];
    const float* ab  = (const float*)d_in[4];

    float* out   = (float*)d_out;                   // [N, 64]
    float* alpha = (float*)d_out + N_NODES * N_HID; // [E]

    k_zero<<<(N_NODES + 255) / 256, 256>>>(ei);
    k_gemm<<<(N_NODES + 31) / 32, 256>>>(x, Wfc, aw);
    k_score_hist<<<(N_EDGES + 255) / 256, 256>>>(ei, ab);
    k_scanA<<<SCAN_BLOCKS, 256>>>();
    k_scanC<<<SCAN_BLOCKS, 256>>>();
    k_place<<<(N_EDGES + 255) / 256, 256>>>(ei, alpha);
    k_accum<<<N_NODES / 16, 256>>>(out);
}

// round 15
// speedup vs baseline: 1.4319x; 1.1068x over previous
#include <cuda_runtime.h>
#include <cstdint>

#define N_NODES 50000
#define N_FEAT  128
#define N_HID   64
#define N_EDGES 800000
#define LRELU   0.05f
#define SCAN_BLOCKS ((N_NODES + 255) / 256)   // 196

// Scratch (static device globals; no allocation allowed)
__device__ float g_ht[N_NODES * N_HID];   // h_transformed  [N, 64]
__device__ float g_e1[N_NODES];           // h_t[i] . a_w[:64]
__device__ float g_e2[N_NODES];           // h_t[i] . a_w[64:]
__device__ float g_hexp[N_EDGES];         // per-edge exp(leakyrelu(z))
__device__ float g_hsum[N_NODES];         // segment sum of hexp by src
__device__ int   g_count[N_NODES];        // out-degree histogram (by src)
__device__ int   g_off[N_NODES];          // CSR offsets
__device__ int   g_cursor[N_NODES];       // placement cursors
__device__ int   g_bsum[SCAN_BLOCKS];     // per-block count sums
__device__ int2  g_ea[N_EDGES];           // packed {dst, h-bits}, segment-ordered
__device__ int   g_idx64;                 // 1 if edge_index is int64, 0 if int32

// ---------------------------------------------------------------------------
__device__ __forceinline__ int load_idx(const void* ei, int row, int e)
{
    long long v;
    if (g_idx64) v = ((const long long*)ei)[(long long)row * N_EDGES + e];
    else         v = ((const int*)ei)[(long long)row * N_EDGES + e];
    if (v < 0) v = 0;
    if (v >= N_NODES) v = N_NODES - 1;
    return (int)v;
}

// ---------------------------------------------------------------------------
// Kernel 0: zero accumulators; block 0 also probes index dtype (ballot).
// ---------------------------------------------------------------------------
__global__ void k_zero(const void* ei)
{
    int i = blockIdx.x * blockDim.x + threadIdx.x;
    if (i < N_NODES) { g_count[i] = 0; g_hsum[i] = 0.0f; }
    if (blockIdx.x == 0 && threadIdx.x < 32) {
        const long long* p = (const long long*)ei;
        int lane = threadIdx.x;
        long long v0 = p[lane];
        long long v1 = p[32 + lane];
        int bad = (v0 < 0 || v0 >= N_NODES || v1 < 0 || v1 >= N_NODES);
        unsigned m = __ballot_sync(0xFFFFFFFFu, bad);
        if (lane == 0) g_idx64 = (m == 0);
    }
}

// ---------------------------------------------------------------------------
// Kernel 1: h_t = x @ W_fc with 2x4 register tiling; fused e1/e2 epilogue.
// Tile 32 rows x 64 cols. Smem 48KB (static limit). (Runs on side stream.)
// ---------------------------------------------------------------------------
__global__ void k_gemm(const float* __restrict__ x,
                       const float* __restrict__ W,
                       const float* __restrict__ aw)
{
    __shared__ float Ws[N_FEAT * N_HID];   // 32 KB  [k][col]
    __shared__ float xs[32 * N_FEAT];      // 16 KB  [row][k]

    const int tid = threadIdx.x;
    const int tx  = tid & 15;
    const int ty  = tid >> 4;
    const int row0 = blockIdx.x * 32;

    {
        const float4* Wg = (const float4*)W;
        float4* Wsm = (float4*)Ws;
        #pragma unroll
        for (int i = 0; i < 8; i++) Wsm[tid + i * 256] = Wg[tid + i * 256];
    }
    {
        float4* xsm = (float4*)xs;
        #pragma unroll
        for (int i = 0; i < 4; i++) {
            int i4 = tid + i * 256;
            int row = row0 + (i4 >> 5);
            float4 v = make_float4(0.f, 0.f, 0.f, 0.f);
            if (row < N_NODES)
                v = ((const float4*)x)[(long long)row * 32 + (i4 & 31)];
            xsm[i4] = v;
        }
    }
    const float4 a1v = ((const float4*)aw)[tx];
    const float4 a2v = ((const float4*)(aw + N_HID))[tx];
    __syncthreads();

    float acc[2][4];
    #pragma unroll
    for (int i = 0; i < 2; i++)
        #pragma unroll
        for (int j = 0; j < 4; j++) acc[i][j] = 0.0f;

    #pragma unroll 8
    for (int k = 0; k < N_FEAT; k++) {
        float4 w = *(const float4*)&Ws[k * N_HID + tx * 4];
        float x0 = xs[(ty * 2 + 0) * N_FEAT + k];
        float x1 = xs[(ty * 2 + 1) * N_FEAT + k];
        acc[0][0] = fmaf(x0, w.x, acc[0][0]);
        acc[0][1] = fmaf(x0, w.y, acc[0][1]);
        acc[0][2] = fmaf(x0, w.z, acc[0][2]);
        acc[0][3] = fmaf(x0, w.w, acc[0][3]);
        acc[1][0] = fmaf(x1, w.x, acc[1][0]);
        acc[1][1] = fmaf(x1, w.y, acc[1][1]);
        acc[1][2] = fmaf(x1, w.z, acc[1][2]);
        acc[1][3] = fmaf(x1, w.w, acc[1][3]);
    }

    #pragma unroll
    for (int i = 0; i < 2; i++) {
        int row = row0 + ty * 2 + i;
        float p1 = acc[i][0] * a1v.x + acc[i][1] * a1v.y +
                   acc[i][2] * a1v.z + acc[i][3] * a1v.w;
        float p2 = acc[i][0] * a2v.x + acc[i][1] * a2v.y +
                   acc[i][2] * a2v.z + acc[i][3] * a2v.w;
        #pragma unroll
        for (int o = 8; o > 0; o >>= 1) {
            p1 += __shfl_xor_sync(0xFFFFFFFFu, p1, o);
            p2 += __shfl_xor_sync(0xFFFFFFFFu, p2, o);
        }
        if (row < N_NODES) {
            *(float4*)&g_ht[(long long)row * N_HID + tx * 4] =
                make_float4(acc[i][0], acc[i][1], acc[i][2], acc[i][3]);
            if (tx == 0) { g_e1[row] = p1; g_e2[row] = p2; }
        }
    }
}

// ---------------------------------------------------------------------------
// Kernel 2: src out-degree histogram (no gemm dependency -> overlaps gemm)
// ---------------------------------------------------------------------------
__global__ void k_hist(const void* __restrict__ ei)
{
    int e = blockIdx.x * blockDim.x + threadIdx.x;
    if (e >= N_EDGES) return;
    atomicAdd(&g_count[load_idx(ei, 0, e)], 1);
}

// ---------------------------------------------------------------------------
// Scan A: per-256-block sums of counts.
// ---------------------------------------------------------------------------
__global__ void k_scanA()
{
    __shared__ int sh[256];
    int idx = blockIdx.x * 256 + threadIdx.x;
    int v = (idx < N_NODES) ? g_count[idx] : 0;
    sh[threadIdx.x] = v;
    __syncthreads();
    for (int o = 128; o > 0; o >>= 1) {
        if (threadIdx.x < o) sh[threadIdx.x] += sh[threadIdx.x + o];
        __syncthreads();
    }
    if (threadIdx.x == 0) g_bsum[blockIdx.x] = sh[0];
}

// ---------------------------------------------------------------------------
// Scan C: each block redundantly scans all 196 block sums (cheap), then its
// local exclusive scan -> offsets + cursors.
// ---------------------------------------------------------------------------
__global__ void k_scanC()
{
    __shared__ int sb[256];
    __shared__ int sh[256];
    int t = threadIdx.x;

    sb[t] = (t < SCAN_BLOCKS) ? g_bsum[t] : 0;
    __syncthreads();
    for (int o = 1; o < 256; o <<= 1) {
        int v = (t >= o) ? sb[t - o] : 0;
        __syncthreads();
        sb[t] += v;
        __syncthreads();
    }
    int base = (blockIdx.x == 0) ? 0 : sb[blockIdx.x - 1];

    int idx = blockIdx.x * 256 + t;
    int v = (idx < N_NODES) ? g_count[idx] : 0;
    sh[t] = v;
    __syncthreads();
    for (int o = 1; o < 256; o <<= 1) {
        int u = (t >= o) ? sh[t - o] : 0;
        __syncthreads();
        sh[t] += u;
        __syncthreads();
    }
    if (idx < N_NODES) {
        int off = base + sh[t] - v;   // exclusive
        g_off[idx] = off;
        g_cursor[idx] = off;
    }
}

// ---------------------------------------------------------------------------
// Kernel 3: fused score + hsum + place (after gemm||scan join).
// 8B record {dst, h}; normalization deferred to accum/alpha.
// ---------------------------------------------------------------------------
__global__ void k_score_place(const void* __restrict__ ei,
                              const float* __restrict__ ab)
{
    int e = blockIdx.x * blockDim.x + threadIdx.x;
    if (e >= N_EDGES) return;
    int s = load_idx(ei, 0, e);
    int d = load_idx(ei, 1, e);
    float z = g_e1[s] + g_e2[d] + ab[0];
    z = (z >= 0.0f) ? z : LRELU * z;
    float h = __expf(z);
    g_hexp[e] = h;
    atomicAdd(&g_hsum[s], h);
    int pos = atomicAdd(&g_cursor[s], 1);
    g_ea[pos] = make_int2(d, __float_as_int(h));
}

// ---------------------------------------------------------------------------
// Kernel 3b: alpha_out[e] = hexp[e] / hsum[src[e]]  (coalesced; overlaps accum)
// ---------------------------------------------------------------------------
__global__ void k_alpha(const void* __restrict__ ei,
                        float* __restrict__ alpha_out)
{
    int e = blockIdx.x * blockDim.x + threadIdx.x;
    if (e >= N_EDGES) return;
    int s = load_idx(ei, 0, e);
    alpha_out[e] = g_hexp[e] / g_hsum[s];
}

// ---------------------------------------------------------------------------
// Kernel 4: per-node accumulate, 16 nodes per 256-thread block.
// out = (sum h*ht[dst]) * inv_hsum. Pure gather, float4.
// ---------------------------------------------------------------------------
__global__ void k_accum(float* __restrict__ out)
{
    const int g = threadIdx.x >> 4;    // node within block (0..15)
    const int q = threadIdx.x & 15;    // float4 lane (channels 4q..4q+3)
    const int s = blockIdx.x * 16 + g; // 3125*16 = 50000 exact
    const int off = g_off[s];
    const int cnt = g_count[s];
    const float inv = (cnt > 0) ? (1.0f / g_hsum[s]) : 0.0f;

    const float4* ht4 = (const float4*)g_ht;

    float4 A0 = make_float4(0.f, 0.f, 0.f, 0.f);
    float4 A1 = make_float4(0.f, 0.f, 0.f, 0.f);
    float4 A2 = make_float4(0.f, 0.f, 0.f, 0.f);
    float4 A3 = make_float4(0.f, 0.f, 0.f, 0.f);

    int j = 0;
    for (; j + 4 <= cnt; j += 4) {
        int2 e0 = g_ea[off + j + 0];
        int2 e1 = g_ea[off + j + 1];
        int2 e2 = g_ea[off + j + 2];
        int2 e3 = g_ea[off + j + 3];
        float4 v0 = ht4[e0.x * 16 + q];
        float4 v1 = ht4[e1.x * 16 + q];
        float4 v2 = ht4[e2.x * 16 + q];
        float4 v3 = ht4[e3.x * 16 + q];
        float a0 = __int_as_float(e0.y);
        float a1 = __int_as_float(e1.y);
        float a2 = __int_as_float(e2.y);
        float a3 = __int_as_float(e3.y);
        A0.x = fmaf(a0, v0.x, A0.x); A0.y = fmaf(a0, v0.y, A0.y);
        A0.z = fmaf(a0, v0.z, A0.z); A0.w = fmaf(a0, v0.w, A0.w);
        A1.x = fmaf(a1, v1.x, A1.x); A1.y = fmaf(a1, v1.y, A1.y);
        A1.z = fmaf(a1, v1.z, A1.z); A1.w = fmaf(a1, v1.w, A1.w);
        A2.x = fmaf(a2, v2.x, A2.x); A2.y = fmaf(a2, v2.y, A2.y);
        A2.z = fmaf(a2, v2.z, A2.z); A2.w = fmaf(a2, v2.w, A2.w);
        A3.x = fmaf(a3, v3.x, A3.x); A3.y = fmaf(a3, v3.y, A3.y);
        A3.z = fmaf(a3, v3.z, A3.z); A3.w = fmaf(a3, v3.w, A3.w);
    }
    for (; j < cnt; j++) {
        int2 ee = g_ea[off + j];
        float4 v = ht4[ee.x * 16 + q];
        float a = __int_as_float(ee.y);
        A0.x = fmaf(a, v.x, A0.x); A0.y = fmaf(a, v.y, A0.y);
        A0.z = fmaf(a, v.z, A0.z); A0.w = fmaf(a, v.w, A0.w);
    }

    float4 R;
    R.x = ((A0.x + A1.x) + (A2.x + A3.x)) * inv;
    R.y = ((A0.y + A1.y) + (A2.y + A3.y)) * inv;
    R.z = ((A0.z + A1.z) + (A2.z + A3.z)) * inv;
    R.w = ((A0.w + A1.w) + (A2.w + A3.w)) * inv;
    ((float4*)out)[s * 16 + q] = R;
}

// ---------------------------------------------------------------------------
extern "C" void kernel_launch(void* const* d_in, const int* in_sizes, int n_in,
                              void* d_out, int out_size)
{
    const float* x   = (const float*)d_in[0];
    const void*  ei  = d_in[1];                 // [2, E] int32 or int64
    const float* Wfc = (const float*)d_in[2];
    const float* aw  = (const float*)d_in[3];
    const float* ab  = (const float*)d_in[4];

    float* out   = (float*)d_out;                   // [N, 64]
    float* alpha = (float*)d_out + N_NODES * N_HID; // [E]

    // Side stream + events, created once (host-side objects only).
    static cudaStream_t s2 = [] { cudaStream_t s; cudaStreamCreate(&s); return s; }();
    static cudaEvent_t evFork = [] { cudaEvent_t e; cudaEventCreateWithFlags(&e, cudaEventDisableTiming); return e; }();
    static cudaEvent_t evGemm = [] { cudaEvent_t e; cudaEventCreateWithFlags(&e, cudaEventDisableTiming); return e; }();
    static cudaEvent_t evSP   = [] { cudaEvent_t e; cudaEventCreateWithFlags(&e, cudaEventDisableTiming); return e; }();
    static cudaEvent_t evAl   = [] { cudaEvent_t e; cudaEventCreateWithFlags(&e, cudaEventDisableTiming); return e; }();

    // Fork: gemm on side stream, index pipeline on main stream.
    cudaEventRecord(evFork, 0);
    cudaStreamWaitEvent(s2, evFork, 0);
    k_gemm<<<(N_NODES + 31) / 32, 256, 0, s2>>>(x, Wfc, aw);
    cudaEventRecord(evGemm, s2);

    k_zero<<<(N_NODES + 255) / 256, 256>>>(ei);
    k_hist<<<(N_EDGES + 255) / 256, 256>>>(ei);
    k_scanA<<<SCAN_BLOCKS, 256>>>();
    k_scanC<<<SCAN_BLOCKS, 256>>>();

    // Join gemm, then fused score+place.
    cudaStreamWaitEvent(0, evGemm, 0);
    k_score_place<<<(N_EDGES + 255) / 256, 256>>>(ei, ab);

    // Fork again: alpha on side stream overlaps accum on main stream.
    cudaEventRecord(evSP, 0);
    cudaStreamWaitEvent(s2, evSP, 0);
    k_alpha<<<(N_EDGES + 255) / 256, 256, 0, s2>>>(ei, alpha);
    cudaEventRecord(evAl, s2);

    k_accum<<<N_NODES / 16, 256>>>(out);
    cudaStreamWaitEvent(0, evAl, 0);   // join so the graph ends on stream 0
}

// round 16
// speedup vs baseline: 1.4667x; 1.0243x over previous
#include <cuda_runtime.h>
#include <cstdint>

#define N_NODES 50000
#define N_FEAT  128
#define N_HID   64
#define N_EDGES 800000
#define LRELU   0.05f
#define CAP     128       // per-node smem h-cache (avg degree 16; fallback recompute)
#define SCAN_BLOCKS ((N_NODES + 255) / 256)   // 196

// Scratch (static device globals; no allocation allowed)
__device__ float g_ht[N_NODES * N_HID];   // h_transformed  [N, 64]
__device__ float g_e1[N_NODES];           // h_t[i] . a_w[:64]
__device__ float g_e2[N_NODES];           // h_t[i] . a_w[64:]
__device__ int   g_count[N_NODES];        // out-degree histogram (by src)
__device__ int   g_off[N_NODES];          // CSR offsets
__device__ int   g_rank[N_EDGES];         // rank of edge within its src segment
__device__ int   g_bsum[SCAN_BLOCKS];     // per-block count sums
__device__ int2  g_ea[N_EDGES];           // packed {dst, edge_id}, segment-ordered
__device__ int   g_idx64;                 // 1 if edge_index is int64, 0 if int32

// ---------------------------------------------------------------------------
__device__ __forceinline__ int load_idx(const void* ei, int row, int e)
{
    long long v;
    if (g_idx64) v = ((const long long*)ei)[(long long)row * N_EDGES + e];
    else         v = ((const int*)ei)[(long long)row * N_EDGES + e];
    if (v < 0) v = 0;
    if (v >= N_NODES) v = N_NODES - 1;
    return (int)v;
}

// ---------------------------------------------------------------------------
// Kernel 0: zero counts; block 0 also probes index dtype (ballot).
// ---------------------------------------------------------------------------
__global__ void k_zero(const void* ei)
{
    int i = blockIdx.x * blockDim.x + threadIdx.x;
    if (i < N_NODES) g_count[i] = 0;
    if (blockIdx.x == 0 && threadIdx.x < 32) {
        const long long* p = (const long long*)ei;
        int lane = threadIdx.x;
        long long v0 = p[lane];
        long long v1 = p[32 + lane];
        int bad = (v0 < 0 || v0 >= N_NODES || v1 < 0 || v1 >= N_NODES);
        unsigned m = __ballot_sync(0xFFFFFFFFu, bad);
        if (lane == 0) g_idx64 = (m == 0);
    }
}

// ---------------------------------------------------------------------------
// Kernel 1: h_t = x @ W_fc with 2x4 register tiling; fused e1/e2 epilogue.
// Runs on the side stream, fully overlapped with the index pipeline.
// ---------------------------------------------------------------------------
__global__ void k_gemm(const float* __restrict__ x,
                       const float* __restrict__ W,
                       const float* __restrict__ aw)
{
    __shared__ float Ws[N_FEAT * N_HID];   // 32 KB  [k][col]
    __shared__ float xs[32 * N_FEAT];      // 16 KB  [row][k]

    const int tid = threadIdx.x;
    const int tx  = tid & 15;
    const int ty  = tid >> 4;
    const int row0 = blockIdx.x * 32;

    {
        const float4* Wg = (const float4*)W;
        float4* Wsm = (float4*)Ws;
        #pragma unroll
        for (int i = 0; i < 8; i++) Wsm[tid + i * 256] = Wg[tid + i * 256];
    }
    {
        float4* xsm = (float4*)xs;
        #pragma unroll
        for (int i = 0; i < 4; i++) {
            int i4 = tid + i * 256;
            int row = row0 + (i4 >> 5);
            float4 v = make_float4(0.f, 0.f, 0.f, 0.f);
            if (row < N_NODES)
                v = ((const float4*)x)[(long long)row * 32 + (i4 & 31)];
            xsm[i4] = v;
        }
    }
    const float4 a1v = ((const float4*)aw)[tx];
    const float4 a2v = ((const float4*)(aw + N_HID))[tx];
    __syncthreads();

    float acc[2][4];
    #pragma unroll
    for (int i = 0; i < 2; i++)
        #pragma unroll
        for (int j = 0; j < 4; j++) acc[i][j] = 0.0f;

    #pragma unroll 8
    for (int k = 0; k < N_FEAT; k++) {
        float4 w = *(const float4*)&Ws[k * N_HID + tx * 4];
        float x0 = xs[(ty * 2 + 0) * N_FEAT + k];
        float x1 = xs[(ty * 2 + 1) * N_FEAT + k];
        acc[0][0] = fmaf(x0, w.x, acc[0][0]);
        acc[0][1] = fmaf(x0, w.y, acc[0][1]);
        acc[0][2] = fmaf(x0, w.z, acc[0][2]);
        acc[0][3] = fmaf(x0, w.w, acc[0][3]);
        acc[1][0] = fmaf(x1, w.x, acc[1][0]);
        acc[1][1] = fmaf(x1, w.y, acc[1][1]);
        acc[1][2] = fmaf(x1, w.z, acc[1][2]);
        acc[1][3] = fmaf(x1, w.w, acc[1][3]);
    }

    #pragma unroll
    for (int i = 0; i < 2; i++) {
        int row = row0 + ty * 2 + i;
        float p1 = acc[i][0] * a1v.x + acc[i][1] * a1v.y +
                   acc[i][2] * a1v.z + acc[i][3] * a1v.w;
        float p2 = acc[i][0] * a2v.x + acc[i][1] * a2v.y +
                   acc[i][2] * a2v.z + acc[i][3] * a2v.w;
        #pragma unroll
        for (int o = 8; o > 0; o >>= 1) {
            p1 += __shfl_xor_sync(0xFFFFFFFFu, p1, o);
            p2 += __shfl_xor_sync(0xFFFFFFFFu, p2, o);
        }
        if (row < N_NODES) {
            *(float4*)&g_ht[(long long)row * N_HID + tx * 4] =
                make_float4(acc[i][0], acc[i][1], acc[i][2], acc[i][3]);
            if (tx == 0) { g_e1[row] = p1; g_e2[row] = p2; }
        }
    }
}

// ---------------------------------------------------------------------------
// Kernel 2: histogram + per-edge rank (rank = position within src segment)
// ---------------------------------------------------------------------------
__global__ void k_hist(const void* __restrict__ ei)
{
    int e = blockIdx.x * blockDim.x + threadIdx.x;
    if (e >= N_EDGES) return;
    int s = load_idx(ei, 0, e);
    g_rank[e] = atomicAdd(&g_count[s], 1);
}

// ---------------------------------------------------------------------------
// Scan A: per-256-block sums of counts.
// ---------------------------------------------------------------------------
__global__ void k_scanA()
{
    __shared__ int sh[256];
    int idx = blockIdx.x * 256 + threadIdx.x;
    int v = (idx < N_NODES) ? g_count[idx] : 0;
    sh[threadIdx.x] = v;
    __syncthreads();
    for (int o = 128; o > 0; o >>= 1) {
        if (threadIdx.x < o) sh[threadIdx.x] += sh[threadIdx.x + o];
        __syncthreads();
    }
    if (threadIdx.x == 0) g_bsum[blockIdx.x] = sh[0];
}

// ---------------------------------------------------------------------------
// Scan C: each block redundantly scans all block sums (cheap), then its
// local exclusive scan -> offsets.
// ---------------------------------------------------------------------------
__global__ void k_scanC()
{
    __shared__ int sb[256];
    __shared__ int sh[256];
    int t = threadIdx.x;

    sb[t] = (t < SCAN_BLOCKS) ? g_bsum[t] : 0;
    __syncthreads();
    for (int o = 1; o < 256; o <<= 1) {
        int v = (t >= o) ? sb[t - o] : 0;
        __syncthreads();
        sb[t] += v;
        __syncthreads();
    }
    int base = (blockIdx.x == 0) ? 0 : sb[blockIdx.x - 1];

    int idx = blockIdx.x * 256 + t;
    int v = (idx < N_NODES) ? g_count[idx] : 0;
    sh[t] = v;
    __syncthreads();
    for (int o = 1; o < 256; o <<= 1) {
        int u = (t >= o) ? sh[t - o] : 0;
        __syncthreads();
        sh[t] += u;
        __syncthreads();
    }
    if (idx < N_NODES) g_off[idx] = base + sh[t] - v;   // exclusive
}

// ---------------------------------------------------------------------------
// Kernel 3: place (index-only, no gemm dependency, no atomics).
// pos = off[src] + rank[e]; one 8B {dst, edge_id} scattered store.
// ---------------------------------------------------------------------------
__global__ void k_place(const void* __restrict__ ei)
{
    int e = blockIdx.x * blockDim.x + threadIdx.x;
    if (e >= N_EDGES) return;
    int s = load_idx(ei, 0, e);
    int d = load_idx(ei, 1, e);
    int pos = g_off[s] + g_rank[e];
    g_ea[pos] = make_int2(d, e);
}

// ---------------------------------------------------------------------------
// Kernel 4: fused score + softmax + accumulate + alpha.
// 16 nodes per 256-thread block; 16 lanes per node.
// Phase i  (per chunk of 16 edges): lane L scores edge j+L (e2 gather + exp),
//          caches h; Phase ii: 16 lanes cooperate on each edge's 64-ch row.
// out[s] = (sum h*ht[dst]) / (sum h);  alpha[e] = h / (sum h).
// ---------------------------------------------------------------------------
__global__ void k_accum(const float* __restrict__ ab,
                        float* __restrict__ out,
                        float* __restrict__ alpha_out)
{
    __shared__ int   sm_d[16][16];
    __shared__ float sm_h[16][16];
    __shared__ float hc[16][CAP];

    const int g = threadIdx.x >> 4;     // node within block (0..15)
    const int L = threadIdx.x & 15;     // lane within group
    const int s = blockIdx.x * 16 + g;  // 3125*16 = 50000 exact
    const int off = g_off[s];
    const int cnt = g_count[s];
    const unsigned gmask = 0xFFFFu << (threadIdx.x & 16);

    const float e1s = g_e1[s];
    const float b   = ab[0];
    const float4* ht4 = (const float4*)g_ht;

    float4 A0 = make_float4(0.f, 0.f, 0.f, 0.f);
    float4 A1 = make_float4(0.f, 0.f, 0.f, 0.f);
    float hsum = 0.0f;

    for (int j = 0; j < cnt; j += 16) {
        int m = cnt - j; if (m > 16) m = 16;

        // phase i: per-lane score
        float h = 0.0f; int dd = 0;
        if (L < m) {
            int2 r = g_ea[off + j + L];
            dd = r.x;
            float z = e1s + g_e2[dd] + b;
            z = (z >= 0.0f) ? z : LRELU * z;
            h = __expf(z);
            hsum += h;
            if (j + L < CAP) hc[g][j + L] = h;
        }
        sm_d[g][L] = dd;
        sm_h[g][L] = h;
        __syncwarp(gmask);

        // phase ii: cooperative row gather-accumulate
        int t = 0;
        for (; t + 2 <= m; t += 2) {
            int   d0 = sm_d[g][t],   d1 = sm_d[g][t + 1];
            float h0 = sm_h[g][t],   h1 = sm_h[g][t + 1];
            float4 v0 = ht4[d0 * 16 + L];
            float4 v1 = ht4[d1 * 16 + L];
            A0.x = fmaf(h0, v0.x, A0.x); A0.y = fmaf(h0, v0.y, A0.y);
            A0.z = fmaf(h0, v0.z, A0.z); A0.w = fmaf(h0, v0.w, A0.w);
            A1.x = fmaf(h1, v1.x, A1.x); A1.y = fmaf(h1, v1.y, A1.y);
            A1.z = fmaf(h1, v1.z, A1.z); A1.w = fmaf(h1, v1.w, A1.w);
        }
        for (; t < m; t++) {
            int   d0 = sm_d[g][t];
            float h0 = sm_h[g][t];
            float4 v0 = ht4[d0 * 16 + L];
            A0.x = fmaf(h0, v0.x, A0.x); A0.y = fmaf(h0, v0.y, A0.y);
            A0.z = fmaf(h0, v0.z, A0.z); A0.w = fmaf(h0, v0.w, A0.w);
        }
        __syncwarp(gmask);   // protect sm_d/sm_h reuse next chunk
    }

    // reduce hsum across the 16 lanes
    #pragma unroll
    for (int o = 8; o > 0; o >>= 1)
        hsum += __shfl_xor_sync(gmask, hsum, o, 16);
    const float inv = (cnt > 0) ? (1.0f / hsum) : 0.0f;

    // alpha pass: scattered 4B stores (records are L1/L2-hot)
    for (int j = L; j < cnt; j += 16) {
        int2 r = g_ea[off + j];
        float h;
        if (j < CAP) {
            h = hc[g][j];
        } else {                     // rare fallback: recompute
            float z = e1s + g_e2[r.x] + b;
            z = (z >= 0.0f) ? z : LRELU * z;
            h = __expf(z);
        }
        alpha_out[r.y] = h * inv;
    }

    float4 R;
    R.x = (A0.x + A1.x) * inv;
    R.y = (A0.y + A1.y) * inv;
    R.z = (A0.z + A1.z) * inv;
    R.w = (A0.w + A1.w) * inv;
    ((float4*)out)[s * 16 + L] = R;
}

// ---------------------------------------------------------------------------
extern "C" void kernel_launch(void* const* d_in, const int* in_sizes, int n_in,
                              void* d_out, int out_size)
{
    const float* x   = (const float*)d_in[0];
    const void*  ei  = d_in[1];                 // [2, E] int32 or int64
    const float* Wfc = (const float*)d_in[2];
    const float* aw  = (const float*)d_in[3];
    const float* ab  = (const float*)d_in[4];

    float* out   = (float*)d_out;                   // [N, 64]
    float* alpha = (float*)d_out + N_NODES * N_HID; // [E]

    static cudaStream_t s2 = [] { cudaStream_t s; cudaStreamCreate(&s); return s; }();
    static cudaEvent_t evFork = [] { cudaEvent_t e; cudaEventCreateWithFlags(&e, cudaEventDisableTiming); return e; }();
    static cudaEvent_t evGemm = [] { cudaEvent_t e; cudaEventCreateWithFlags(&e, cudaEventDisableTiming); return e; }();

    // Fork: gemm on side stream; index pipeline (no gemm deps) on main.
    cudaEventRecord(evFork, 0);
    cudaStreamWaitEvent(s2, evFork, 0);
    k_gemm<<<(N_NODES + 31) / 32, 256, 0, s2>>>(x, Wfc, aw);
    cudaEventRecord(evGemm, s2);

    k_zero<<<(N_NODES + 255) / 256, 256>>>(ei);
    k_hist<<<(N_EDGES + 255) / 256, 256>>>(ei);
    k_scanA<<<SCAN_BLOCKS, 256>>>();
    k_scanC<<<SCAN_BLOCKS, 256>>>();
    k_place<<<(N_EDGES + 255) / 256, 256>>>(ei);

    // Join gemm, then the fused score+softmax+accumulate kernel.
    cudaStreamWaitEvent(0, evGemm, 0);
    k_accum<<<N_NODES / 16, 256>>>(ab, out, alpha);
}

// round 17
// speedup vs baseline: 1.4831x; 1.0112x over previous
#include <cuda_runtime.h>
#include <cstdint>

#define N_NODES 50000
#define N_FEAT  128
#define N_HID   64
#define N_EDGES 800000
#define LRELU   0.05f
#define CAP     128       // per-node smem h-cache (avg degree 16; fallback recompute)
#define SCAN_BLOCKS ((N_NODES + 255) / 256)   // 196

// Scratch (static device globals; no allocation allowed)
__device__ float g_ht[N_NODES * N_HID];   // h_transformed  [N, 64]
__device__ float g_e1[N_NODES];           // h_t[i] . a_w[:64]
__device__ float g_e2[N_NODES];           // h_t[i] . a_w[64:]
__device__ int   g_count[N_NODES];        // out-degree histogram (by src)
__device__ int   g_off[N_NODES];          // CSR offsets
__device__ int   g_rank[N_EDGES];         // rank of edge within its src segment
__device__ int   g_bsum[SCAN_BLOCKS];     // per-block count sums
__device__ int2  g_ea[N_EDGES];           // packed {dst, edge_id}, segment-ordered
__device__ int   g_idx64;                 // 1 if edge_index is int64, 0 if int32

// ---------------------------------------------------------------------------
__device__ __forceinline__ int clampn(long long v)
{
    if (v < 0) v = 0;
    if (v >= N_NODES) v = N_NODES - 1;
    return (int)v;
}

__device__ __forceinline__ int load_idx(const void* ei, int row, int e)
{
    long long v;
    if (g_idx64) v = ((const long long*)ei)[(long long)row * N_EDGES + e];
    else         v = ((const int*)ei)[(long long)row * N_EDGES + e];
    return clampn(v);
}

// ---------------------------------------------------------------------------
// Kernel 0: zero counts; block 0 also probes index dtype (ballot).
// ---------------------------------------------------------------------------
__global__ void k_zero(const void* ei)
{
    int i = blockIdx.x * blockDim.x + threadIdx.x;
    if (i < N_NODES) g_count[i] = 0;
    if (blockIdx.x == 0 && threadIdx.x < 32) {
        const long long* p = (const long long*)ei;
        int lane = threadIdx.x;
        long long v0 = p[lane];
        long long v1 = p[32 + lane];
        int bad = (v0 < 0 || v0 >= N_NODES || v1 < 0 || v1 >= N_NODES);
        unsigned m = __ballot_sync(0xFFFFFFFFu, bad);
        if (lane == 0) g_idx64 = (m == 0);
    }
}

// ---------------------------------------------------------------------------
// Kernel 1: h_t = x @ W_fc with 2x4 register tiling; fused e1/e2 epilogue.
// Runs on the side stream, fully overlapped with the index pipeline.
// ---------------------------------------------------------------------------
__global__ void k_gemm(const float* __restrict__ x,
                       const float* __restrict__ W,
                       const float* __restrict__ aw)
{
    __shared__ float Ws[N_FEAT * N_HID];   // 32 KB  [k][col]
    __shared__ float xs[32 * N_FEAT];      // 16 KB  [row][k]

    const int tid = threadIdx.x;
    const int tx  = tid & 15;
    const int ty  = tid >> 4;
    const int row0 = blockIdx.x * 32;

    {
        const float4* Wg = (const float4*)W;
        float4* Wsm = (float4*)Ws;
        #pragma unroll
        for (int i = 0; i < 8; i++) Wsm[tid + i * 256] = Wg[tid + i * 256];
    }
    {
        float4* xsm = (float4*)xs;
        #pragma unroll
        for (int i = 0; i < 4; i++) {
            int i4 = tid + i * 256;
            int row = row0 + (i4 >> 5);
            float4 v = make_float4(0.f, 0.f, 0.f, 0.f);
            if (row < N_NODES)
                v = ((const float4*)x)[(long long)row * 32 + (i4 & 31)];
            xsm[i4] = v;
        }
    }
    const float4 a1v = ((const float4*)aw)[tx];
    const float4 a2v = ((const float4*)(aw + N_HID))[tx];
    __syncthreads();

    float acc[2][4];
    #pragma unroll
    for (int i = 0; i < 2; i++)
        #pragma unroll
        for (int j = 0; j < 4; j++) acc[i][j] = 0.0f;

    #pragma unroll 8
    for (int k = 0; k < N_FEAT; k++) {
        float4 w = *(const float4*)&Ws[k * N_HID + tx * 4];
        float x0 = xs[(ty * 2 + 0) * N_FEAT + k];
        float x1 = xs[(ty * 2 + 1) * N_FEAT + k];
        acc[0][0] = fmaf(x0, w.x, acc[0][0]);
        acc[0][1] = fmaf(x0, w.y, acc[0][1]);
        acc[0][2] = fmaf(x0, w.z, acc[0][2]);
        acc[0][3] = fmaf(x0, w.w, acc[0][3]);
        acc[1][0] = fmaf(x1, w.x, acc[1][0]);
        acc[1][1] = fmaf(x1, w.y, acc[1][1]);
        acc[1][2] = fmaf(x1, w.z, acc[1][2]);
        acc[1][3] = fmaf(x1, w.w, acc[1][3]);
    }

    #pragma unroll
    for (int i = 0; i < 2; i++) {
        int row = row0 + ty * 2 + i;
        float p1 = acc[i][0] * a1v.x + acc[i][1] * a1v.y +
                   acc[i][2] * a1v.z + acc[i][3] * a1v.w;
        float p2 = acc[i][0] * a2v.x + acc[i][1] * a2v.y +
                   acc[i][2] * a2v.z + acc[i][3] * a2v.w;
        #pragma unroll
        for (int o = 8; o > 0; o >>= 1) {
            p1 += __shfl_xor_sync(0xFFFFFFFFu, p1, o);
            p2 += __shfl_xor_sync(0xFFFFFFFFu, p2, o);
        }
        if (row < N_NODES) {
            *(float4*)&g_ht[(long long)row * N_HID + tx * 4] =
                make_float4(acc[i][0], acc[i][1], acc[i][2], acc[i][3]);
            if (tx == 0) { g_e1[row] = p1; g_e2[row] = p2; }
        }
    }
}

// ---------------------------------------------------------------------------
// Kernel 2: histogram + per-edge rank, 4 edges/thread (4 atomics in flight).
// src row read as int4 (int32 path) for coalescing.
// ---------------------------------------------------------------------------
__global__ void k_hist(const void* __restrict__ ei)
{
    int t = blockIdx.x * blockDim.x + threadIdx.x;
    int e0 = t * 4;
    if (e0 >= N_EDGES) return;

    int s[4];
    if (!g_idx64) {
        int4 v = ((const int4*)ei)[t];
        s[0] = clampn(v.x); s[1] = clampn(v.y);
        s[2] = clampn(v.z); s[3] = clampn(v.w);
    } else {
        const long long* p = (const long long*)ei;
        #pragma unroll
        for (int i = 0; i < 4; i++) s[i] = clampn(p[e0 + i]);
    }
    int r0 = atomicAdd(&g_count[s[0]], 1);
    int r1 = atomicAdd(&g_count[s[1]], 1);
    int r2 = atomicAdd(&g_count[s[2]], 1);
    int r3 = atomicAdd(&g_count[s[3]], 1);
    *(int4*)&g_rank[e0] = make_int4(r0, r1, r2, r3);
}

// ---------------------------------------------------------------------------
// Scan A: per-256-block sums of counts.
// ---------------------------------------------------------------------------
__global__ void k_scanA()
{
    __shared__ int sh[256];
    int idx = blockIdx.x * 256 + threadIdx.x;
    int v = (idx < N_NODES) ? g_count[idx] : 0;
    sh[threadIdx.x] = v;
    __syncthreads();
    for (int o = 128; o > 0; o >>= 1) {
        if (threadIdx.x < o) sh[threadIdx.x] += sh[threadIdx.x + o];
        __syncthreads();
    }
    if (threadIdx.x == 0) g_bsum[blockIdx.x] = sh[0];
}

// ---------------------------------------------------------------------------
// Scan C: each block redundantly scans all block sums (cheap), then its
// local exclusive scan -> offsets.
// ---------------------------------------------------------------------------
__global__ void k_scanC()
{
    __shared__ int sb[256];
    __shared__ int sh[256];
    int t = threadIdx.x;

    sb[t] = (t < SCAN_BLOCKS) ? g_bsum[t] : 0;
    __syncthreads();
    for (int o = 1; o < 256; o <<= 1) {
        int v = (t >= o) ? sb[t - o] : 0;
        __syncthreads();
        sb[t] += v;
        __syncthreads();
    }
    int base = (blockIdx.x == 0) ? 0 : sb[blockIdx.x - 1];

    int idx = blockIdx.x * 256 + t;
    int v = (idx < N_NODES) ? g_count[idx] : 0;
    sh[t] = v;
    __syncthreads();
    for (int o = 1; o < 256; o <<= 1) {
        int u = (t >= o) ? sh[t - o] : 0;
        __syncthreads();
        sh[t] += u;
        __syncthreads();
    }
    if (idx < N_NODES) g_off[idx] = base + sh[t] - v;   // exclusive
}

// ---------------------------------------------------------------------------
// Kernel 3: place, 4 edges/thread (4 independent gathers + scatters).
// pos = off[src] + rank[e]; one 8B {dst, edge_id} scattered store each.
// ---------------------------------------------------------------------------
__global__ void k_place(const void* __restrict__ ei)
{
    int t = blockIdx.x * blockDim.x + threadIdx.x;
    int e0 = t * 4;
    if (e0 >= N_EDGES) return;

    int s[4], d[4];
    if (!g_idx64) {
        int4 vs = ((const int4*)ei)[t];
        int4 vd = ((const int4*)((const int*)ei + N_EDGES))[t];
        s[0] = clampn(vs.x); s[1] = clampn(vs.y);
        s[2] = clampn(vs.z); s[3] = clampn(vs.w);
        d[0] = clampn(vd.x); d[1] = clampn(vd.y);
        d[2] = clampn(vd.z); d[3] = clampn(vd.w);
    } else {
        const long long* ps = (const long long*)ei;
        const long long* pd = ps + N_EDGES;
        #pragma unroll
        for (int i = 0; i < 4; i++) { s[i] = clampn(ps[e0 + i]); d[i] = clampn(pd[e0 + i]); }
    }
    int4 r = *(const int4*)&g_rank[e0];

    int p0 = g_off[s[0]] + r.x;
    int p1 = g_off[s[1]] + r.y;
    int p2 = g_off[s[2]] + r.z;
    int p3 = g_off[s[3]] + r.w;
    g_ea[p0] = make_int2(d[0], e0 + 0);
    g_ea[p1] = make_int2(d[1], e0 + 1);
    g_ea[p2] = make_int2(d[2], e0 + 2);
    g_ea[p3] = make_int2(d[3], e0 + 3);
}

// ---------------------------------------------------------------------------
// Kernel 4: fused score + softmax + accumulate + alpha.
// 16 nodes per 256-thread block; 16 lanes per node. Phase ii uses 4
// independent accumulators for MLP-4 on the row gathers.
// ---------------------------------------------------------------------------
__global__ void k_accum(const float* __restrict__ ab,
                        float* __restrict__ out,
                        float* __restrict__ alpha_out)
{
    __shared__ int   sm_d[16][16];
    __shared__ float sm_h[16][16];
    __shared__ float hc[16][CAP];

    const int g = threadIdx.x >> 4;     // node within block (0..15)
    const int L = threadIdx.x & 15;     // lane within group
    const int s = blockIdx.x * 16 + g;  // 3125*16 = 50000 exact
    const int off = g_off[s];
    const int cnt = g_count[s];
    const unsigned gmask = 0xFFFFu << (threadIdx.x & 16);

    const float e1s = g_e1[s];
    const float b   = ab[0];
    const float4* ht4 = (const float4*)g_ht;

    float4 A0 = make_float4(0.f, 0.f, 0.f, 0.f);
    float4 A1 = make_float4(0.f, 0.f, 0.f, 0.f);
    float4 A2 = make_float4(0.f, 0.f, 0.f, 0.f);
    float4 A3 = make_float4(0.f, 0.f, 0.f, 0.f);
    float hsum = 0.0f;

    for (int j = 0; j < cnt; j += 16) {
        int m = cnt - j; if (m > 16) m = 16;

        // phase i: per-lane score
        float h = 0.0f; int dd = 0;
        if (L < m) {
            int2 r = g_ea[off + j + L];
            dd = r.x;
            float z = e1s + g_e2[dd] + b;
            z = (z >= 0.0f) ? z : LRELU * z;
            h = __expf(z);
            hsum += h;
            if (j + L < CAP) hc[g][j + L] = h;
        }
        sm_d[g][L] = dd;
        sm_h[g][L] = h;
        __syncwarp(gmask);

        // phase ii: cooperative row gather-accumulate, MLP 4
        int t = 0;
        for (; t + 4 <= m; t += 4) {
            int   d0 = sm_d[g][t],     d1 = sm_d[g][t + 1];
            int   d2 = sm_d[g][t + 2], d3 = sm_d[g][t + 3];
            float h0 = sm_h[g][t],     h1 = sm_h[g][t + 1];
            float h2 = sm_h[g][t + 2], h3 = sm_h[g][t + 3];
            float4 v0 = ht4[d0 * 16 + L];
            float4 v1 = ht4[d1 * 16 + L];
            float4 v2 = ht4[d2 * 16 + L];
            float4 v3 = ht4[d3 * 16 + L];
            A0.x = fmaf(h0, v0.x, A0.x); A0.y = fmaf(h0, v0.y, A0.y);
            A0.z = fmaf(h0, v0.z, A0.z); A0.w = fmaf(h0, v0.w, A0.w);
            A1.x = fmaf(h1, v1.x, A1.x); A1.y = fmaf(h1, v1.y, A1.y);
            A1.z = fmaf(h1, v1.z, A1.z); A1.w = fmaf(h1, v1.w, A1.w);
            A2.x = fmaf(h2, v2.x, A2.x); A2.y = fmaf(h2, v2.y, A2.y);
            A2.z = fmaf(h2, v2.z, A2.z); A2.w = fmaf(h2, v2.w, A2.w);
            A3.x = fmaf(h3, v3.x, A3.x); A3.y = fmaf(h3, v3.y, A3.y);
            A3.z = fmaf(h3, v3.z, A3.z); A3.w = fmaf(h3, v3.w, A3.w);
        }
        for (; t < m; t++) {
            int   d0 = sm_d[g][t];
            float h0 = sm_h[g][t];
            float4 v0 = ht4[d0 * 16 + L];
            A0.x = fmaf(h0, v0.x, A0.x); A0.y = fmaf(h0, v0.y, A0.y);
            A0.z = fmaf(h0, v0.z, A0.z); A0.w = fmaf(h0, v0.w, A0.w);
        }
        __syncwarp(gmask);   // protect sm_d/sm_h reuse next chunk
    }

    // reduce hsum across the 16 lanes
    #pragma unroll
    for (int o = 8; o > 0; o >>= 1)
        hsum += __shfl_xor_sync(gmask, hsum, o, 16);
    const float inv = (cnt > 0) ? (1.0f / hsum) : 0.0f;

    // alpha pass: scattered 4B stores (records are L1/L2-hot)
    for (int j = L; j < cnt; j += 16) {
        int2 r = g_ea[off + j];
        float h;
        if (j < CAP) {
            h = hc[g][j];
        } else {                     // rare fallback: recompute
            float z = e1s + g_e2[r.x] + b;
            z = (z >= 0.0f) ? z : LRELU * z;
            h = __expf(z);
        }
        alpha_out[r.y] = h * inv;
    }

    float4 R;
    R.x = ((A0.x + A1.x) + (A2.x + A3.x)) * inv;
    R.y = ((A0.y + A1.y) + (A2.y + A3.y)) * inv;
    R.z = ((A0.z + A1.z) + (A2.z + A3.z)) * inv;
    R.w = ((A0.w + A1.w) + (A2.w + A3.w)) * inv;
    ((float4*)out)[s * 16 + L] = R;
}

// ---------------------------------------------------------------------------
extern "C" void kernel_launch(void* const* d_in, const int* in_sizes, int n_in,
                              void* d_out, int out_size)
{
    const float* x   = (const float*)d_in[0];
    const void*  ei  = d_in[1];                 // [2, E] int32 or int64
    const float* Wfc = (const float*)d_in[2];
    const float* aw  = (const float*)d_in[3];
    const float* ab  = (const float*)d_in[4];

    float* out   = (float*)d_out;                   // [N, 64]
    float* alpha = (float*)d_out + N_NODES * N_HID; // [E]

    static cudaStream_t s2 = [] { cudaStream_t s; cudaStreamCreate(&s); return s; }();
    static cudaEvent_t evFork = [] { cudaEvent_t e; cudaEventCreateWithFlags(&e, cudaEventDisableTiming); return e; }();
    static cudaEvent_t evGemm = [] { cudaEvent_t e; cudaEventCreateWithFlags(&e, cudaEventDisableTiming); return e; }();

    // Fork: gemm on side stream; index pipeline (no gemm deps) on main.
    cudaEventRecord(evFork, 0);
    cudaStreamWaitEvent(s2, evFork, 0);
    k_gemm<<<(N_NODES + 31) / 32, 256, 0, s2>>>(x, Wfc, aw);
    cudaEventRecord(evGemm, s2);

    k_zero<<<(N_NODES + 255) / 256, 256>>>(ei);
    k_hist<<<(N_EDGES / 4 + 255) / 256, 256>>>(ei);
    k_scanA<<<SCAN_BLOCKS, 256>>>();
    k_scanC<<<SCAN_BLOCKS, 256>>>();
    k_place<<<(N_EDGES / 4 + 255) / 256, 256>>>(ei);

    // Join gemm, then the fused score+softmax+accumulate kernel.
    cudaStreamWaitEvent(0, evGemm, 0);
    k_accum<<<N_NODES / 16, 256>>>(ab, out, alpha);
}